// round 11
// baseline (speedup 1.0000x reference)
#include <cuda_runtime.h>
#include <stdint.h>

// B=256 graphs, M=512 atoms, K=33 neighbors (incl self), radius 5.0
// Output float32 concatenated: src[E], dst[E], dist[E], mask[E], E = B*M*K
#define BGRAPH 256
#define MPTS   512
#define KNN    33
#define QPB    256                       // queries per CTA (2 CTAs per graph)
#define NCTA   ((BGRAPH * MPTS) / QPB)   // 512
#define CAP    42                        // collect buffer capacity per query
#define RADIUS 5.0f

typedef unsigned long long ull;

// Shared layout (per CTA):
//   tile : float4[512]                      8192 B
//   bufD : u32 [CAP+1][QPB+1] (padded)     44204 B   (histograms overlay bufD+bufI;
//   bufI : u16 [CAP+1][QPB+2] (padded)     22188 B    phases separated by __syncthreads)
// total 74584 B -> 3 CTAs/SM
#define BUFD_STRIDE (QPB + 1)
#define BUFI_STRIDE (QPB + 2)
#define TILE_BYTES  (MPTS * 16)
#define BUFD_BYTES  ((CAP + 1) * BUFD_STRIDE * 4)
#define BUFI_BYTES  ((CAP + 1) * BUFI_STRIDE * 2)
#define SMEM_BYTES  (TILE_BYTES + BUFD_BYTES + BUFI_BYTES)
// Hist overlay: histA[32][256] + histB[32][256] u32 words, each packing two u16 counters.
static_assert(64 * QPB * 4 <= BUFD_BYTES + BUFI_BYTES, "hist overlay must fit in buf region");

// Composite 48-bit key: (d2_bits << 16) | idx  -> exact (d2, idx) lexicographic order,
// matching lax.top_k stability (ascending d2, lower index first on ties).
__device__ __forceinline__ ull ldk(const uint32_t* bD, const uint16_t* bI, int i) {
    return ((ull)bD[i * BUFD_STRIDE] << 16) | bI[i * BUFI_STRIDE];
}
__device__ __forceinline__ void stk(uint32_t* bD, uint16_t* bI, int i, ull k) {
    bD[i * BUFD_STRIDE] = (uint32_t)(k >> 16);
    bI[i * BUFI_STRIDE] = (uint16_t)k;
}

// Branchless fixed-depth max-heap sift (round 10): the old early-exit sift loop was the
// kernel's only divergent region — per-level BSSY/BSYNC with all warps arriving together
// after a barrier, nothing to hide behind. This version always walks 6 levels (covers any
// heap size <= 42: root escape path 0-1-3-7-15-31 is 5 moves), with clamped child loads
// and an 'alive' flag gating a predicated move. Identical final heap state: moves happen
// exactly while children exceed val; once not, alive=0 freezes p; val lands at p.
__device__ __forceinline__ void sift_b(uint32_t* bD, uint16_t* bI, int start, int nn, ull val) {
    int p = start;
    bool alive = true;
    #pragma unroll
    for (int it = 0; it < 6; ++it) {
        int l = 2 * p + 1;
        int r = l + 1;
        int lc = l < nn ? l : 0;                 // clamped safe reads
        int rc = r < nn ? r : 0;
        ull cl = ldk(bD, bI, lc);
        ull cr = ldk(bD, bI, rc);
        bool rbig = (r < nn) && (cr > cl);
        ull c  = rbig ? cr : cl;
        int ci = rbig ? r : l;
        bool move = alive && (l < nn) && (c > val);
        if (move) { stk(bD, bI, p, c); p = ci; } // predicated short arm, no BSSY
        alive = move;
    }
    stk(bD, bI, p, val);
}

extern "C" __global__ void __launch_bounds__(QPB, 3)
knn_graph_kernel(const float* __restrict__ pos, float* __restrict__ out)
{
    extern __shared__ unsigned char smem[];
    float4*   tile = (float4*)smem;
    uint32_t* bufD = (uint32_t*)(smem + TILE_BYTES);
    uint16_t* bufI = (uint16_t*)(smem + TILE_BYTES + BUFD_BYTES);
    uint32_t* histA = (uint32_t*)(smem + TILE_BYTES);          // overlays buf region (dead
    uint32_t* histB = histA + 32 * QPB;                        //  after the barrier below)

    const int cta  = blockIdx.x;
    const int g    = cta >> 1;
    const int qoff = (cta & 1) * QPB;
    const int base = g * MPTS;
    const int tid  = threadIdx.x;

    // ---- Stage positions: coalesced load, pack float4(x,y,z,|p|^2) ----
    {
        float* raw = (float*)(smem + TILE_BYTES);      // scratch in buf region
        const float* gp = pos + (size_t)base * 3;
        for (int i = tid; i < MPTS * 3; i += QPB) raw[i] = gp[i];
        __syncthreads();
        for (int i = tid; i < MPTS; i += QPB) {
            float x = raw[i * 3 + 0], y = raw[i * 3 + 1], z = raw[i * 3 + 2];
            tile[i] = make_float4(x, y, z, x * x + y * y + z * z);
        }
        __syncthreads();
    }

    const int q = qoff + tid;                          // this thread's query (0..511 in graph)
    const float4 me = tile[q];
    const float px = me.x, py = me.y, pz = me.z, sq = me.w;

    // ---- Threshold refinement: per-thread 32-bin histograms, packed dual-array RMW ----
    // (proven round-8 scheme: broadcast tile reads are near-free; A/B arrays give MLP 2
    //  on the alias-serialized LDS->IADD->STS chain; u16 halves pack 2 sub-counters/word)
    //   - low-clamp bin 0 keeps cumulative counts EXACT
    //   - high-clamp bin 31 inflates nT -> only trust/break on bstar < 31; refine anyway
    uint32_t* hAq = histA + tid;                       // hAq[b<<8], conflict-free columns
    uint32_t* hBq = histB + tid;
    uint32_t lo = 120u << 23;                          // octave bins: d2 in [2^-7, 2^24)
    int      sh = 23;
    uint32_t Tsel = 0xFFFFFFFFu;

    for (int pass = 0; pass < 10; ++pass) {
        #pragma unroll
        for (int b = 0; b < 32; ++b) { hAq[b << 8] = 0u; hBq[b << 8] = 0u; }

        #pragma unroll 2
        for (int c = 0; c < MPTS; c += 4) {
            float4 t0 = tile[c + 0];
            float4 t1 = tile[c + 1];
            float4 t2 = tile[c + 2];
            float4 t3 = tile[c + 3];
            float d0 = fmaf(-2.0f, px * t0.x + py * t0.y + pz * t0.z, sq + t0.w);
            float d1 = fmaf(-2.0f, px * t1.x + py * t1.y + pz * t1.z, sq + t1.w);
            float d2 = fmaf(-2.0f, px * t2.x + py * t2.y + pz * t2.z, sq + t2.w);
            float d3 = fmaf(-2.0f, px * t3.x + py * t3.y + pz * t3.z, sq + t3.w);
            // negative-ulp d2 bits -> negative signed diff -> clamped to bin 0: exact
            int b0 = (int)(__float_as_uint(d0) - lo) >> sh;
            int b1 = (int)(__float_as_uint(d1) - lo) >> sh;
            int b2 = (int)(__float_as_uint(d2) - lo) >> sh;
            int b3 = (int)(__float_as_uint(d3) - lo) >> sh;
            b0 = b0 < 0 ? 0 : (b0 > 31 ? 31 : b0);
            b1 = b1 < 0 ? 0 : (b1 > 31 ? 31 : b1);
            b2 = b2 < 0 ? 0 : (b2 > 31 ? 31 : b2);
            b3 = b3 < 0 ? 0 : (b3 > 31 ? 31 : b3);
            hAq[b0 << 8] += 1u;
            hAq[b1 << 8] += 0x10000u;
            hBq[b2 << 8] += 1u;
            hBq[b3 << 8] += 0x10000u;
        }

        uint32_t cumP = 0, nT = 0;                     // packed cumulative (lo/hi halves)
        int bstar = -1;
        #pragma unroll
        for (int b = 0; b < 32; ++b) {
            cumP += hAq[b << 8] + hBq[b << 8];
            uint32_t tot = (cumP & 0xFFFFu) + (cumP >> 16);
            if (bstar < 0 && tot >= KNN) { bstar = b; nT = tot; }
        }

        if (bstar < 31) {
            Tsel = lo + ((uint32_t)(bstar + 1) << sh); // exact: nT keys strictly below Tsel
            if (nT <= CAP) break;
        }
        // refine into boundary bin (uniform for bstar==31: tiles the old bin exactly)
        lo += (uint32_t)bstar << sh;
        sh  = sh > 5 ? sh - 5 : 0;
    }

    // hist overlays bufD/bufI and warps exit the pass loop after different pass counts;
    // without this barrier early warps' collect writes race late warps' live histograms.
    __syncthreads();

    // ---- Branch-free collect: all candidates with key < Tsel ----
    uint32_t* bDq = bufD + tid;
    uint16_t* bIq = bufI + tid;
    uint32_t cnt = 0;
    #pragma unroll 8
    for (int c = 0; c < MPTS; ++c) {
        float4 t = tile[c];
        float dot = px * t.x + py * t.y + pz * t.z;
        float d2  = fmaxf(fmaf(-2.0f, dot, sq + t.w), 0.0f);  // normalize -eps -> +0 for stored keys
        uint32_t key = __float_as_uint(d2);
        uint32_t slot = cnt < CAP ? cnt : CAP;         // row CAP = scratch (absorbs non-passing writes)
        bDq[slot * BUFD_STRIDE] = key;                 // unconditional store; a passing candidate
        bIq[slot * BUFI_STRIDE] = (uint16_t)c;         // claims the slot by advancing cnt
        cnt += (key < Tsel) ? 1u : 0u;
    }
    uint32_t n = cnt;
    if (n > CAP) n = CAP;                              // safety rail; slots 0..CAP-1 valid
    if (n < KNN) {                                     // safety rail: pad with +inf keys, valid idx 0
        for (uint32_t i = n; i < KNN; ++i) stk(bDq, bIq, (int)i, ((ull)0xFFFFFFFFu << 16));
        n = KNN;
    }

    // ---- Exact top-33 + ascending sort over <=42 elements, fully convergent ----
    for (int i = KNN / 2 - 1; i >= 0; --i) {           // heapify (branchless sifts)
        ull v = ldk(bDq, bIq, i);
        sift_b(bDq, bIq, i, KNN, v);
    }
    ull root = ldk(bDq, bIq, 0);
    for (uint32_t i = KNN; i < n; ++i) {               // branchless insert: sifting the
        ull v = ldk(bDq, bIq, (int)i);                 // current max when v >= root is a
        ull vv = v < root ? v : root;                  // provable no-op (settles at p=0)
        sift_b(bDq, bIq, 0, KNN, vv);
        root = ldk(bDq, bIq, 0);
    }
    for (int end = KNN - 1; end > 0; --end) {          // heapsort -> ascending (d2, idx)
        ull maxv = ldk(bDq, bIq, 0);
        ull last = ldk(bDq, bIq, end);
        stk(bDq, bIq, end, maxv);
        sift_b(bDq, bIq, 0, end, last);
    }
    __syncwarp();                                      // output reads same-warp lanes' columns only

    // ---- Coalesced output: warp covers its 32 queries' 32*33 edges linearly ----
    const int warp = tid >> 5;
    const int lane = tid & 31;
    const int q0   = warp << 5;                        // within CTA
    const long E   = (long)BGRAPH * MPTS * KNN;        // 4,325,376
    const long eBase = (long)(base + qoff + q0) * KNN;

    for (int j = lane; j < 32 * KNN; j += 32) {
        int qi = j / KNN;
        int k  = j - qi * KNN;
        int qlocal = q0 + qi;
        int c  = (int)bufI[k * BUFI_STRIDE + qlocal];
        int qq = qoff + qlocal;

        float4 a = tile[c];                            // src = neighbor
        float4 b = tile[qq];                           // dst = center
        float dx = a.x - b.x, dy = a.y - b.y, dz = a.z - b.z;
        float dd = dx * dx + dy * dy + dz * dz;        // reference recomputes from gathered endpoints
        float dist = (dd > 0.0f) ? sqrtf(dd) : 0.0f;

        long e = eBase + j;
        out[e]         = (float)(base + c);
        out[E + e]     = (float)(base + qq);
        out[2 * E + e] = dist;
        out[3 * E + e] = (dist <= RADIUS) ? 1.0f : 0.0f;
    }
}

extern "C" void kernel_launch(void* const* d_in, const int* in_sizes, int n_in,
                              void* d_out, int out_size) {
    const float* pos = (const float*)d_in[0];          // [B*M, 3] float32 (batch input unused: uniform)
    float* out = (float*)d_out;
    cudaFuncSetAttribute(knn_graph_kernel,
                         cudaFuncAttributeMaxDynamicSharedMemorySize, (int)SMEM_BYTES);
    knn_graph_kernel<<<NCTA, QPB, SMEM_BYTES>>>(pos, out);
}

// round 12
// speedup vs baseline: 1.0744x; 1.0744x over previous
#include <cuda_runtime.h>
#include <stdint.h>

// B=256 graphs, M=512 atoms, K=33 neighbors (incl self), radius 5.0
// Output float32 concatenated: src[E], dst[E], dist[E], mask[E], E = B*M*K
#define BGRAPH 256
#define MPTS   512
#define KNN    33
#define QPB    256                       // queries per CTA (2 CTAs per graph)
#define NCTA   ((BGRAPH * MPTS) / QPB)   // 512
#define CAP    58                        // collect capacity (1/8-octave nT = 33+Poisson(~4.6) << 58)
#define NB     16                        // histogram bins per pass
#define RADIUS 5.0f

typedef unsigned long long ull;

// Shared layout (per CTA) — slim (round 11):
//   tile : float4[512]                                   8192 B
//   over : max( histA+histB u32[16][256] x2 = 32768 B,
//               bufI u16[CAP+1][QPB+2]     = 30444 B )  32768 B
// total 40960 B -> 5 CTAs/SM allowed; all 512 CTAs resident in ONE wave (vs R8's 1.15 waves)
#define BUFI_STRIDE (QPB + 2)
#define TILE_BYTES  (MPTS * 16)
#define OVER_BYTES  (2 * NB * QPB * 4)
#define SMEM_BYTES  (TILE_BYTES + OVER_BYTES)
static_assert((CAP + 1) * BUFI_STRIDE * 2 <= OVER_BYTES, "bufI must fit in overlay");

// Recompute the composite 48-bit key (d2_bits<<16 | idx) for buffer slot i from the tile.
// Deterministic: same FP expression + same inputs as collect -> identical bits -> the exact
// (d2, idx) lexicographic order (lax.top_k stability) is preserved without storing keys.
__device__ __forceinline__ ull key_of(const uint16_t* bI, const float4* tile,
                                      float px, float py, float pz, float sq, int i) {
    int c = bI[i * BUFI_STRIDE];
    float4 t = tile[c];
    float d2 = fmaxf(fmaf(-2.0f, px * t.x + py * t.y + pz * t.z, sq + t.w), 0.0f);
    return ((ull)__float_as_uint(d2) << 16) | (unsigned)c;
}

// Early-exit max-heap sift on the idx-only buffer (R8-style divergent sift: it beat the
// branchless variant in round 10). Only u16 indices are stored; keys are recomputed.
__device__ __forceinline__ void sift_down(uint16_t* bI, const float4* tile,
                                          float px, float py, float pz, float sq,
                                          int start, int nn, ull val) {
    int p = start;
    for (;;) {
        int l = 2 * p + 1;
        if (l >= nn) break;
        ull c = key_of(bI, tile, px, py, pz, sq, l);
        int ci = l;
        if (l + 1 < nn) {
            ull cr = key_of(bI, tile, px, py, pz, sq, l + 1);
            if (cr > c) { c = cr; ci = l + 1; }
        }
        if (c <= val) break;
        bI[p * BUFI_STRIDE] = (uint16_t)c;     // low 16 bits of composite key = idx
        p = ci;
    }
    bI[p * BUFI_STRIDE] = (uint16_t)val;
}

extern "C" __global__ void __launch_bounds__(QPB, 5)
knn_graph_kernel(const float* __restrict__ pos, float* __restrict__ out)
{
    extern __shared__ unsigned char smem[];
    float4*   tile  = (float4*)smem;
    uint32_t* histA = (uint32_t*)(smem + TILE_BYTES);   // u32[16][256], u16-packed halves
    uint32_t* histB = histA + NB * QPB;                 // second array -> 4 RMW chains total
    uint16_t* bufI  = (uint16_t*)(smem + TILE_BYTES);   // overlays hist (dead after barrier)

    const int cta  = blockIdx.x;
    const int g    = cta >> 1;
    const int qoff = (cta & 1) * QPB;
    const int base = g * MPTS;
    const int tid  = threadIdx.x;

    // ---- Stage positions: coalesced load, pack float4(x,y,z,|p|^2) ----
    {
        float* raw = (float*)(smem + TILE_BYTES);       // scratch in overlay region
        const float* gp = pos + (size_t)base * 3;
        for (int i = tid; i < MPTS * 3; i += QPB) raw[i] = gp[i];
        __syncthreads();
        for (int i = tid; i < MPTS; i += QPB) {
            float x = raw[i * 3 + 0], y = raw[i * 3 + 1], z = raw[i * 3 + 2];
            tile[i] = make_float4(x, y, z, x * x + y * y + z * z);
        }
        __syncthreads();
    }

    const int q = qoff + tid;                           // this thread's query (0..511 in graph)
    const float4 me = tile[q];
    const float px = me.x, py = me.y, pz = me.z, sq = me.w;

    // ---- Threshold refinement: 16-bin per-thread histograms, 4 independent RMW chains ----
    // Pass 1: 2-octave bins (sh=24) covering d2 in [2^-7, 2^25) -> exact window.
    // Pass 2: 1/8-octave bins (sh=20) tiling the boundary bin -> nT = 33 + ~Poisson(4.6),
    // always <= CAP=58 in practice -> deterministic 2 passes per warp (same as R8, half smem).
    //   - low-clamp bin 0 keeps cumulative counts EXACT
    //   - high-clamp bin 15 inflates nT -> only trust/break on bstar < 15; refine anyway
    uint32_t* hAq = histA + tid;                        // hAq[b<<8], conflict-free columns
    uint32_t* hBq = histB + tid;
    uint32_t lo = 120u << 23;                           // window start: d2 = 2^-7
    int      sh = 24;
    uint32_t Tsel = 0xFFFFFFFFu;

    for (int pass = 0; pass < 8; ++pass) {
        #pragma unroll
        for (int b = 0; b < NB; ++b) { hAq[b << 8] = 0u; hBq[b << 8] = 0u; }

        #pragma unroll 2
        for (int c = 0; c < MPTS; c += 4) {
            float4 t0 = tile[c + 0];
            float4 t1 = tile[c + 1];
            float4 t2 = tile[c + 2];
            float4 t3 = tile[c + 3];
            float d0 = fmaf(-2.0f, px * t0.x + py * t0.y + pz * t0.z, sq + t0.w);
            float d1 = fmaf(-2.0f, px * t1.x + py * t1.y + pz * t1.z, sq + t1.w);
            float d2 = fmaf(-2.0f, px * t2.x + py * t2.y + pz * t2.z, sq + t2.w);
            float d3 = fmaf(-2.0f, px * t3.x + py * t3.y + pz * t3.z, sq + t3.w);
            // negative-ulp d2 bits -> negative signed diff -> clamped to bin 0: exact
            int b0 = (int)(__float_as_uint(d0) - lo) >> sh;
            int b1 = (int)(__float_as_uint(d1) - lo) >> sh;
            int b2 = (int)(__float_as_uint(d2) - lo) >> sh;
            int b3 = (int)(__float_as_uint(d3) - lo) >> sh;
            b0 = b0 < 0 ? 0 : (b0 > NB - 1 ? NB - 1 : b0);
            b1 = b1 < 0 ? 0 : (b1 > NB - 1 ? NB - 1 : b1);
            b2 = b2 < 0 ? 0 : (b2 > NB - 1 ? NB - 1 : b2);
            b3 = b3 < 0 ? 0 : (b3 > NB - 1 ? NB - 1 : b3);
            hAq[b0 << 8] += 1u;                         // 4 sub-counter chains: A-lo, A-hi,
            hAq[b1 << 8] += 0x10000u;                   // B-lo, B-hi (each counts <=128,
            hBq[b2 << 8] += 1u;                         // u16 halves never overflow/carry)
            hBq[b3 << 8] += 0x10000u;
        }

        uint32_t cumP = 0, nT = 0;                      // packed cumulative (lo/hi halves)
        int bstar = -1;
        #pragma unroll
        for (int b = 0; b < NB; ++b) {
            cumP += hAq[b << 8] + hBq[b << 8];
            uint32_t tot = (cumP & 0xFFFFu) + (cumP >> 16);
            if (bstar < 0 && tot >= KNN) { bstar = b; nT = tot; }
        }

        if (bstar < NB - 1) {
            Tsel = lo + ((uint32_t)(bstar + 1) << sh);  // exact: nT keys strictly below Tsel
            if (nT <= CAP) break;
        }
        // refine into boundary bin (uniform for bstar==15: tiles the old bin exactly)
        lo += (uint32_t)bstar << sh;
        sh  = sh > 4 ? sh - 4 : 0;
    }

    // bufI overlays the histograms and warps exit the pass loop at different pass counts;
    // this barrier keeps early warps' collect writes from racing late warps' live hists.
    __syncthreads();

    // ---- Branch-free collect (idx only): all candidates with key < Tsel ----
    uint16_t* bIq = bufI + tid;
    uint32_t cnt = 0;
    #pragma unroll 8
    for (int c = 0; c < MPTS; ++c) {
        float4 t = tile[c];
        float dot = px * t.x + py * t.y + pz * t.z;
        float d2  = fmaxf(fmaf(-2.0f, dot, sq + t.w), 0.0f);   // normalize -eps -> +0
        uint32_t key = __float_as_uint(d2);
        uint32_t slot = cnt < CAP ? cnt : CAP;          // row CAP = scratch (absorbs non-passing)
        bIq[slot * BUFI_STRIDE] = (uint16_t)c;          // unconditional store; passing candidate
        cnt += (key < Tsel) ? 1u : 0u;                  // claims the slot by advancing cnt
    }
    uint32_t n = cnt;
    if (n > CAP) n = CAP;                               // safety rail; slots 0..CAP-1 valid
    if (n < KNN) {                                      // safety rail (unreachable for sane data):
        uint16_t pad = bIq[0];                          // pad with a valid idx, memory-safe
        for (uint32_t i = n; i < KNN; ++i) bIq[i * BUFI_STRIDE] = pad;
        n = KNN;
    }

    // ---- Exact top-33 + ascending sort over <=58 idx entries (keys recomputed on demand) ----
    for (int i = KNN / 2 - 1; i >= 0; --i) {            // heapify
        ull v = key_of(bIq, tile, px, py, pz, sq, i);
        sift_down(bIq, tile, px, py, pz, sq, i, KNN, v);
    }
    ull root = key_of(bIq, tile, px, py, pz, sq, 0);
    for (uint32_t i = KNN; i < n; ++i) {                // inserts (mean ~4-5 extras)
        ull v = key_of(bIq, tile, px, py, pz, sq, (int)i);
        if (v < root) {
            sift_down(bIq, tile, px, py, pz, sq, 0, KNN, v);
            root = key_of(bIq, tile, px, py, pz, sq, 0);
        }
    }
    for (int end = KNN - 1; end > 0; --end) {           // heapsort -> ascending (d2, idx)
        uint16_t maxi = bIq[0];
        ull last = key_of(bIq, tile, px, py, pz, sq, end);
        bIq[end * BUFI_STRIDE] = maxi;
        sift_down(bIq, tile, px, py, pz, sq, 0, end, last);
    }
    __syncwarp();                                       // output reads same-warp lanes' columns

    // ---- Coalesced output: warp covers its 32 queries' 32*33 edges linearly ----
    const int warp = tid >> 5;
    const int lane = tid & 31;
    const int q0   = warp << 5;                         // within CTA
    const long E   = (long)BGRAPH * MPTS * KNN;         // 4,325,376
    long e = (long)(base + qoff + q0) * KNN + lane;

    int qi = 0, k = lane;                               // incremental j/33, j%33 (no divide)
    for (int t = 0; t < KNN; ++t) {                     // 33 steps x 32 lanes = 1056 edges
        int qlocal = q0 + qi;
        int c  = (int)bufI[k * BUFI_STRIDE + qlocal];
        int qq = qoff + qlocal;

        float4 a = tile[c];                             // src = neighbor
        float4 b = tile[qq];                            // dst = center
        float dx = a.x - b.x, dy = a.y - b.y, dz = a.z - b.z;
        float dd = dx * dx + dy * dy + dz * dz;         // reference recomputes from endpoints
        float dist = (dd > 0.0f) ? sqrtf(dd) : 0.0f;

        out[e]         = (float)(base + c);
        out[E + e]     = (float)(base + qq);
        out[2 * E + e] = dist;
        out[3 * E + e] = (dist <= RADIUS) ? 1.0f : 0.0f;

        e += 32;
        k += 32;
        if (k >= KNN) { k -= KNN; ++qi; }               // step 32 < 33: at most one wrap
    }
}

extern "C" void kernel_launch(void* const* d_in, const int* in_sizes, int n_in,
                              void* d_out, int out_size) {
    const float* pos = (const float*)d_in[0];           // [B*M, 3] float32 (batch input unused)
    float* out = (float*)d_out;
    cudaFuncSetAttribute(knn_graph_kernel,
                         cudaFuncAttributeMaxDynamicSharedMemorySize, (int)SMEM_BYTES);
    knn_graph_kernel<<<NCTA, QPB, SMEM_BYTES>>>(pos, out);
}